// round 2
// baseline (speedup 1.0000x reference)
#include <cuda_runtime.h>

#define BN 16384
#define RN 237
#define DN 128
#define CN 50
#define TB 24          // triples per CTA
#define ROWS 48        // 2*TB rows in the GEMM tile
#define NTH 192
#define MAXWORK 960    // >= 237 + 16384/24
#define SXP 132        // padded row stride for X/C tile (16B-aligned, avoids conflicts)

__device__ int  g_count[RN];
__device__ int  g_offset[RN];
__device__ int  g_cursor[RN];
__device__ int  g_sorted[BN];
__device__ int  g_nwork;
__device__ int2 g_work[MAXWORK];

// ---------------- sort-by-relation kernels ----------------

__global__ void k_init() {
    int t = threadIdx.x;
    if (t < RN) { g_count[t] = 0; g_cursor[t] = 0; }
}

__global__ void k_hist(const int* __restrict__ triples) {
    int i = blockIdx.x * blockDim.x + threadIdx.x;
    if (i < BN) atomicAdd(&g_count[triples[3*i + 1]], 1);
}

__global__ void k_scan() {
    __shared__ int sc[RN], so[RN], sw[RN];
    int t = threadIdx.x;
    if (t < RN) sc[t] = g_count[t];
    __syncthreads();
    if (t == 0) {
        int off = 0, w = 0;
        for (int r = 0; r < RN; r++) {
            so[r] = off; sw[r] = w;
            off += sc[r];
            w += (sc[r] + TB - 1) / TB;
        }
        g_nwork = w;
    }
    __syncthreads();
    if (t < RN) {
        g_offset[t] = so[t];
        int cnt = sc[t];
        int nch = (cnt + TB - 1) / TB;
        for (int ch = 0; ch < nch; ch++) {
            g_work[sw[t] + ch] = make_int2(so[t] + ch * TB, min(TB, cnt - ch * TB));
        }
    }
}

__global__ void k_scatter(const int* __restrict__ triples) {
    int i = blockIdx.x * blockDim.x + threadIdx.x;
    if (i < BN) {
        int r = triples[3*i + 1];
        int pos = g_offset[r] + atomicAdd(&g_cursor[r], 1);
        g_sorted[pos] = i;
    }
}

// ---------------- main fused kernel ----------------

__device__ __forceinline__ void cp16(void* s, const void* g) {
    unsigned u = (unsigned)__cvta_generic_to_shared(s);
    asm volatile("cp.async.cg.shared.global [%0], [%1], 16;" :: "r"(u), "l"(g));
}

extern __shared__ float smem[];

__global__ void __launch_bounds__(NTH) k_main(
    const int* __restrict__ triples, const float* __restrict__ ent,
    const float* __restrict__ rel, const float* __restrict__ W,
    const float* __restrict__ cw, const float* __restrict__ cb,
    const float* __restrict__ fcw, const float* __restrict__ fcb,
    float* __restrict__ out)
{
    // smem layout (floats)
    float* sX   = smem;                 // 48*132 = 6336 (reused as C after GEMM)
    float* sW   = sX + ROWS * SXP;      // 2 x 16 x 128 = 4096
    float* sFC  = sW + 4096;            // 6400
    float* sRel = sFC + 6400;           // 128
    float* sCw0 = sRel + DN;            // 50
    float* sCw1 = sCw0 + CN;
    float* sCw2 = sCw1 + CN;
    float* sCb  = sCw2 + CN;
    float* sRed = sCb + CN;             // 16
    int*   sEid = (int*)(sRed + 16);    // 48

    int bid = blockIdx.x;
    if (bid >= g_nwork) return;
    int tid = threadIdx.x;
    int2 wi = g_work[bid];
    int start = wi.x, cnt = wi.y;

    // group 0: fc_w + rel row + W panel 0
    for (int i = tid; i < 1600; i += NTH)
        cp16(sFC + i*4, fcw + i*4);

    int r = triples[3 * g_sorted[start] + 1];

    for (int i = tid; i < 32; i += NTH)
        cp16(sRel + i*4, rel + (size_t)r * DN + i*4);

    const float* gw = W + (size_t)r * DN * DN;
    for (int i = tid; i < 512; i += NTH)
        cp16(sW + i*4, gw + i*4);
    asm volatile("cp.async.commit_group;");

    if (tid < CN) {
        sCw0[tid] = cw[tid*3 + 0];
        sCw1[tid] = cw[tid*3 + 1];
        sCw2[tid] = cw[tid*3 + 2];
        sCb[tid]  = cb[tid];
    }
    if (tid < ROWS) {
        int eid = 0;
        if (tid < 2*cnt) {
            int ti = g_sorted[start + (tid >> 1)];
            eid = triples[3*ti + ((tid & 1) ? 2 : 0)];
        }
        sEid[tid] = eid;
    }
    __syncthreads();

    // gather X rows (zero-pad unused rows)
    for (int e = tid; e < ROWS * 32; e += NTH) {
        int row = e >> 5, k4 = e & 31;
        float4 v = make_float4(0.f, 0.f, 0.f, 0.f);
        if (row < 2*cnt)
            v = *(const float4*)(ent + (size_t)sEid[row] * DN + k4*4);
        *(float4*)(sX + row * SXP + k4*4) = v;
    }

    int c = tid & 31, rg = tid >> 5;
    float4 acc[8];
    #pragma unroll
    for (int i = 0; i < 8; i++) acc[i] = make_float4(0.f, 0.f, 0.f, 0.f);

    const float* xbase = sX + rg * 8 * SXP;

    for (int p = 0; p < 8; p++) {
        if (p < 7) {
            const float* gp = gw + (p + 1) * 2048;
            float* sp = sW + ((p + 1) & 1) * 2048;
            for (int i = tid; i < 512; i += NTH)
                cp16(sp + i*4, gp + i*4);
            asm volatile("cp.async.commit_group;");
            asm volatile("cp.async.wait_group 1;" ::: "memory");
        } else {
            asm volatile("cp.async.wait_group 0;" ::: "memory");
        }
        __syncthreads();
        const float* wp = sW + (p & 1) * 2048;
        const float* xp = xbase + p * 16;
        #pragma unroll
        for (int kk = 0; kk < 16; kk++) {
            float4 b = *(const float4*)(wp + kk * DN + c*4);
            #pragma unroll
            for (int i = 0; i < 8; i++) {
                float a = xp[i * SXP + kk];
                acc[i].x = fmaf(a, b.x, acc[i].x);
                acc[i].y = fmaf(a, b.y, acc[i].y);
                acc[i].z = fmaf(a, b.z, acc[i].z);
                acc[i].w = fmaf(a, b.w, acc[i].w);
            }
        }
        __syncthreads();
    }

    // write C (projections) into sX region
    float* sC = sX;
    #pragma unroll
    for (int i = 0; i < 8; i++)
        *(float4*)(sC + (rg*8 + i) * SXP + c*4) = acc[i];
    __syncthreads();

    // epilogue: conv(3->50) + ReLU + FC dot, 4 triples per pass
    float fcb0 = fcb[0];
    int d = tid;
    float relv = (tid < DN) ? sRel[d] : 0.f;

    for (int u0 = 0; u0 < TB; u0 += 4) {
        float part0 = 0.f, part1 = 0.f, part2 = 0.f, part3 = 0.f;
        if (tid < DN) {
            float ph0 = sC[(2*u0 + 0)*SXP + d], pt0 = sC[(2*u0 + 1)*SXP + d];
            float ph1 = sC[(2*u0 + 2)*SXP + d], pt1 = sC[(2*u0 + 3)*SXP + d];
            float ph2 = sC[(2*u0 + 4)*SXP + d], pt2 = sC[(2*u0 + 5)*SXP + d];
            float ph3 = sC[(2*u0 + 6)*SXP + d], pt3 = sC[(2*u0 + 7)*SXP + d];
            #pragma unroll 10
            for (int cc = 0; cc < CN; cc++) {
                float w0 = sCw0[cc], w1 = sCw1[cc], w2 = sCw2[cc], bb = sCb[cc];
                float base = fmaf(w1, relv, bb);
                float fw = sFC[cc * DN + d];
                float s0 = fmaxf(fmaf(w0, ph0, fmaf(w2, pt0, base)), 0.f);
                float s1 = fmaxf(fmaf(w0, ph1, fmaf(w2, pt1, base)), 0.f);
                float s2 = fmaxf(fmaf(w0, ph2, fmaf(w2, pt2, base)), 0.f);
                float s3 = fmaxf(fmaf(w0, ph3, fmaf(w2, pt3, base)), 0.f);
                part0 = fmaf(s0, fw, part0);
                part1 = fmaf(s1, fw, part1);
                part2 = fmaf(s2, fw, part2);
                part3 = fmaf(s3, fw, part3);
            }
            #pragma unroll
            for (int o = 16; o; o >>= 1) {
                part0 += __shfl_xor_sync(0xffffffffu, part0, o);
                part1 += __shfl_xor_sync(0xffffffffu, part1, o);
                part2 += __shfl_xor_sync(0xffffffffu, part2, o);
                part3 += __shfl_xor_sync(0xffffffffu, part3, o);
            }
            if ((tid & 31) == 0) {
                int w = tid >> 5;
                sRed[w*4 + 0] = part0; sRed[w*4 + 1] = part1;
                sRed[w*4 + 2] = part2; sRed[w*4 + 3] = part3;
            }
        }
        __syncthreads();
        if (tid < 4) {
            int u = u0 + tid;
            if (u < cnt) {
                float v = sRed[tid] + sRed[4 + tid] + sRed[8 + tid] + sRed[12 + tid] + fcb0;
                out[g_sorted[start + u]] = v;
            }
        }
        __syncthreads();
    }
}

// ---------------- launch ----------------

extern "C" void kernel_launch(void* const* d_in, const int* in_sizes, int n_in,
                              void* d_out, int out_size)
{
    const int*   triples = (const int*)d_in[0];
    const float* ent     = (const float*)d_in[1];
    const float* rel     = (const float*)d_in[2];
    const float* W       = (const float*)d_in[3];
    const float* cw      = (const float*)d_in[4];
    const float* cb      = (const float*)d_in[5];
    const float* fcw     = (const float*)d_in[6];
    const float* fcb     = (const float*)d_in[7];
    float* out = (float*)d_out;

    size_t shbytes = (size_t)(ROWS*SXP + 4096 + 6400 + DN + 4*CN + 16) * 4 + ROWS * 4;
    cudaFuncSetAttribute(k_main, cudaFuncAttributeMaxDynamicSharedMemorySize, (int)(shbytes + 256));

    k_init<<<1, 256>>>();
    k_hist<<<(BN + 255) / 256, 256>>>(triples);
    k_scan<<<1, 256>>>();
    k_scatter<<<(BN + 255) / 256, 256>>>(triples);
    k_main<<<MAXWORK, NTH, shbytes>>>(triples, ent, rel, W, cw, cb, fcw, fcb, out);
}

// round 6
// speedup vs baseline: 1.1605x; 1.1605x over previous
#include <cuda_runtime.h>

#define BN 16384
#define RN 237
#define DN 128
#define CN 50
#define TB 24          // triples per CTA
#define ROWS 48        // 2*TB rows in the GEMM tile
#define NTH 192
#define MAXWORK 960    // >= 237 + 16384/24
#define SXP 132        // padded row stride for X/C tile
#define HB 16          // hist/scatter blocks
#define HT 1024        // hist/scatter threads

__device__ int  g_part[HB][RN];
__device__ int  g_offset[RN];
__device__ int  g_cursor[RN];
__device__ int  g_sorted[BN];
__device__ int  g_nwork;
__device__ int2 g_work[MAXWORK];

// ---------------- sort-by-relation (3 kernels, low-contention) ----------------

__global__ void __launch_bounds__(HT) k_hist(const int* __restrict__ triples) {
    __shared__ int h[4][RN];
    int t = threadIdx.x;
    for (int i = t; i < 4 * RN; i += HT) (&h[0][0])[i] = 0;
    __syncthreads();
    int i = blockIdx.x * HT + t;                 // BN == HB*HT exactly
    int r = triples[3 * i + 1];
    atomicAdd(&h[t & 3][r], 1);
    __syncthreads();
    for (int rr = t; rr < RN; rr += HT)
        g_part[blockIdx.x][rr] = h[0][rr] + h[1][rr] + h[2][rr] + h[3][rr];
}

__global__ void k_scan() {
    __shared__ int cnt[256], coff[256], woff[256];
    int t = threadIdx.x;
    int c = 0;
    if (t < RN) {
        #pragma unroll
        for (int b = 0; b < HB; b++) c += g_part[b][t];
    }
    int nch = (c + TB - 1) / TB;
    cnt[t] = c; coff[t] = c; woff[t] = nch;
    __syncthreads();
    #pragma unroll
    for (int s = 1; s < 256; s <<= 1) {
        int a = (t >= s) ? coff[t - s] : 0;
        int b = (t >= s) ? woff[t - s] : 0;
        __syncthreads();
        coff[t] += a; woff[t] += b;
        __syncthreads();
    }
    if (t < RN) {
        int off   = coff[t] - cnt[t];   // exclusive
        int wbase = woff[t] - nch;
        g_offset[t] = off;
        g_cursor[t] = 0;
        for (int ch = 0; ch < nch; ch++)
            g_work[wbase + ch] = make_int2(off + ch * TB, min(TB, c - ch * TB));
    }
    if (t == 255) g_nwork = woff[255];
}

__global__ void __launch_bounds__(HT) k_scatter(const int* __restrict__ triples) {
    __shared__ int h[4][RN];
    __shared__ int base[RN];
    __shared__ int lcur[RN];
    int t = threadIdx.x;
    for (int i = t; i < 4 * RN; i += HT) (&h[0][0])[i] = 0;
    __syncthreads();
    int i = blockIdx.x * HT + t;
    int r = triples[3 * i + 1];
    atomicAdd(&h[t & 3][r], 1);
    __syncthreads();
    for (int rr = t; rr < RN; rr += HT) {
        int cc = h[0][rr] + h[1][rr] + h[2][rr] + h[3][rr];
        base[rr] = cc ? atomicAdd(&g_cursor[rr], cc) : 0;
        lcur[rr] = 0;
    }
    __syncthreads();
    int p = base[r] + atomicAdd(&lcur[r], 1);
    g_sorted[g_offset[r] + p] = i;
}

// ---------------- main fused kernel ----------------

__device__ __forceinline__ void cp16(void* s, const void* g) {
    unsigned u = (unsigned)__cvta_generic_to_shared(s);
    asm volatile("cp.async.cg.shared.global [%0], [%1], 16;" :: "r"(u), "l"(g));
}

extern __shared__ float smem[];

__global__ void __launch_bounds__(NTH) k_main(
    const int* __restrict__ triples, const float* __restrict__ ent,
    const float* __restrict__ rel, const float* __restrict__ W,
    const float* __restrict__ cw, const float* __restrict__ cb,
    const float* __restrict__ fcw, const float* __restrict__ fcb,
    float* __restrict__ out)
{
    float* sX   = smem;                 // 48*132 (reused as C after GEMM)
    float* sW   = sX + ROWS * SXP;      // 2 x 16 x 128
    float* sFC  = sW + 4096;            // 6400
    float* sRel = sFC + 6400;           // 128
    float* sCw0 = sRel + DN;
    float* sCw1 = sCw0 + CN;
    float* sCw2 = sCw1 + CN;
    float* sCb  = sCw2 + CN;
    float* sRed = sCb + CN;             // 16
    int*   sEid = (int*)(sRed + 16);    // 48

    int bid = blockIdx.x;
    if (bid >= g_nwork) return;
    int tid = threadIdx.x;
    int2 wi = g_work[bid];
    int start = wi.x, cnt = wi.y;

    int r = triples[3 * g_sorted[start] + 1];
    const float* gw = W + (size_t)r * DN * DN;

    // group 0: rel row + W panel 0
    for (int i = tid; i < 32; i += NTH)
        cp16(sRel + i*4, rel + (size_t)r * DN + i*4);
    for (int i = tid; i < 512; i += NTH)
        cp16(sW + i*4, gw + i*4);
    asm volatile("cp.async.commit_group;");

    // group 1: fc_w (not needed until epilogue)
    for (int i = tid; i < 1600; i += NTH)
        cp16(sFC + i*4, fcw + i*4);
    asm volatile("cp.async.commit_group;");

    if (tid < CN) {
        sCw0[tid] = cw[tid*3 + 0];
        sCw1[tid] = cw[tid*3 + 1];
        sCw2[tid] = cw[tid*3 + 2];
        sCb[tid]  = cb[tid];
    }
    if (tid < ROWS) {
        int eid = 0;
        if (tid < 2*cnt) {
            int ti = g_sorted[start + (tid >> 1)];
            eid = triples[3*ti + ((tid & 1) ? 2 : 0)];
        }
        sEid[tid] = eid;
    }
    __syncthreads();

    // gather X rows (zero-pad unused rows)
    for (int e = tid; e < ROWS * 32; e += NTH) {
        int row = e >> 5, k4 = e & 31;
        float4 v = make_float4(0.f, 0.f, 0.f, 0.f);
        if (row < 2*cnt)
            v = *(const float4*)(ent + (size_t)sEid[row] * DN + k4*4);
        *(float4*)(sX + row * SXP + k4*4) = v;
    }

    int c = tid & 31, rg = tid >> 5;
    float4 acc[8];
    #pragma unroll
    for (int i = 0; i < 8; i++) acc[i] = make_float4(0.f, 0.f, 0.f, 0.f);

    const float* xbase = sX + rg * 8 * SXP;

    for (int p = 0; p < 8; p++) {
        if (p < 7) {
            const float* gp = gw + (p + 1) * 2048;
            float* sp = sW + ((p + 1) & 1) * 2048;
            for (int i = tid; i < 512; i += NTH)
                cp16(sp + i*4, gp + i*4);
            asm volatile("cp.async.commit_group;");
            if (p == 0)
                asm volatile("cp.async.wait_group 2;" ::: "memory");  // W0 done; FC+W1 in flight
            else
                asm volatile("cp.async.wait_group 1;" ::: "memory");  // W(p) done
        } else {
            asm volatile("cp.async.wait_group 0;" ::: "memory");
        }
        __syncthreads();
        const float* wp = sW + (p & 1) * 2048;
        const float* xp = xbase + p * 16;
        #pragma unroll
        for (int kk = 0; kk < 16; kk++) {
            float4 b = *(const float4*)(wp + kk * DN + c*4);
            #pragma unroll
            for (int i = 0; i < 8; i++) {
                float a = xp[i * SXP + kk];
                acc[i].x = fmaf(a, b.x, acc[i].x);
                acc[i].y = fmaf(a, b.y, acc[i].y);
                acc[i].z = fmaf(a, b.z, acc[i].z);
                acc[i].w = fmaf(a, b.w, acc[i].w);
            }
        }
        __syncthreads();
    }

    // write C (projections) into sX region
    float* sC = sX;
    #pragma unroll
    for (int i = 0; i < 8; i++)
        *(float4*)(sC + (rg*8 + i) * SXP + c*4) = acc[i];
    __syncthreads();

    // epilogue: conv(3->50) + ReLU + FC dot, 4 triples per pass
    float fcb0 = fcb[0];
    int d = tid;
    float relv = (tid < DN) ? sRel[d] : 0.f;

    for (int u0 = 0; u0 < TB; u0 += 4) {
        float part0 = 0.f, part1 = 0.f, part2 = 0.f, part3 = 0.f;
        if (tid < DN) {
            float ph0 = sC[(2*u0 + 0)*SXP + d], pt0 = sC[(2*u0 + 1)*SXP + d];
            float ph1 = sC[(2*u0 + 2)*SXP + d], pt1 = sC[(2*u0 + 3)*SXP + d];
            float ph2 = sC[(2*u0 + 4)*SXP + d], pt2 = sC[(2*u0 + 5)*SXP + d];
            float ph3 = sC[(2*u0 + 6)*SXP + d], pt3 = sC[(2*u0 + 7)*SXP + d];
            #pragma unroll 10
            for (int cc = 0; cc < CN; cc++) {
                float w0 = sCw0[cc], w1 = sCw1[cc], w2 = sCw2[cc], bb = sCb[cc];
                float base = fmaf(w1, relv, bb);
                float fw = sFC[cc * DN + d];
                float s0 = fmaxf(fmaf(w0, ph0, fmaf(w2, pt0, base)), 0.f);
                float s1 = fmaxf(fmaf(w0, ph1, fmaf(w2, pt1, base)), 0.f);
                float s2 = fmaxf(fmaf(w0, ph2, fmaf(w2, pt2, base)), 0.f);
                float s3 = fmaxf(fmaf(w0, ph3, fmaf(w2, pt3, base)), 0.f);
                part0 = fmaf(s0, fw, part0);
                part1 = fmaf(s1, fw, part1);
                part2 = fmaf(s2, fw, part2);
                part3 = fmaf(s3, fw, part3);
            }
            #pragma unroll
            for (int o = 16; o; o >>= 1) {
                part0 += __shfl_xor_sync(0xffffffffu, part0, o);
                part1 += __shfl_xor_sync(0xffffffffu, part1, o);
                part2 += __shfl_xor_sync(0xffffffffu, part2, o);
                part3 += __shfl_xor_sync(0xffffffffu, part3, o);
            }
            if ((tid & 31) == 0) {
                int w = tid >> 5;
                sRed[w*4 + 0] = part0; sRed[w*4 + 1] = part1;
                sRed[w*4 + 2] = part2; sRed[w*4 + 3] = part3;
            }
        }
        __syncthreads();
        if (tid < 4) {
            int u = u0 + tid;
            if (u < cnt) {
                float v = sRed[tid] + sRed[4 + tid] + sRed[8 + tid] + sRed[12 + tid] + fcb0;
                out[g_sorted[start + u]] = v;
            }
        }
        __syncthreads();
    }
}

// ---------------- launch ----------------

extern "C" void kernel_launch(void* const* d_in, const int* in_sizes, int n_in,
                              void* d_out, int out_size)
{
    const int*   triples = (const int*)d_in[0];
    const float* ent     = (const float*)d_in[1];
    const float* rel     = (const float*)d_in[2];
    const float* W       = (const float*)d_in[3];
    const float* cw      = (const float*)d_in[4];
    const float* cb      = (const float*)d_in[5];
    const float* fcw     = (const float*)d_in[6];
    const float* fcb     = (const float*)d_in[7];
    float* out = (float*)d_out;

    size_t shbytes = (size_t)(ROWS*SXP + 4096 + 6400 + DN + 4*CN + 16) * 4 + ROWS * 4;
    cudaFuncSetAttribute(k_main, cudaFuncAttributeMaxDynamicSharedMemorySize, (int)(shbytes + 256));

    k_hist<<<HB, HT>>>(triples);
    k_scan<<<1, 256>>>();
    k_scatter<<<HB, HT>>>(triples);
    k_main<<<MAXWORK, NTH, shbytes>>>(triples, ent, rel, W, cw, cb, fcw, fcb, out);
}

// round 7
// speedup vs baseline: 1.1742x; 1.0118x over previous
#include <cuda_runtime.h>

#define BN 16384
#define RN 237
#define DN 128
#define CN 50
#define TB 24          // triples per CTA
#define ROWS 48        // 2*TB rows in the GEMM tile
#define NTH 192
#define MAXWORK 960    // >= 237 + 16384/24
#define SXP 132        // padded row stride for X/C tile
#define HB 16          // hist/scatter blocks
#define HT 1024        // hist/scatter threads

__device__ int  g_part[HB][RN];
__device__ int  g_offset[RN];
__device__ int  g_cursor[RN];
__device__ int  g_sorted[BN];
__device__ int  g_nwork;
__device__ int2 g_work[MAXWORK];

// ---------------- sort-by-relation (3 kernels, low-contention) ----------------

__global__ void __launch_bounds__(HT) k_hist(const int* __restrict__ triples) {
    __shared__ int h[4][RN];
    int t = threadIdx.x;
    for (int i = t; i < 4 * RN; i += HT) (&h[0][0])[i] = 0;
    __syncthreads();
    int i = blockIdx.x * HT + t;                 // BN == HB*HT exactly
    int r = triples[3 * i + 1];
    atomicAdd(&h[t & 3][r], 1);
    __syncthreads();
    for (int rr = t; rr < RN; rr += HT)
        g_part[blockIdx.x][rr] = h[0][rr] + h[1][rr] + h[2][rr] + h[3][rr];
}

__global__ void k_scan() {
    __shared__ int cnt[256], coff[256], woff[256];
    int t = threadIdx.x;
    int c = 0;
    if (t < RN) {
        #pragma unroll
        for (int b = 0; b < HB; b++) c += g_part[b][t];
    }
    int nch = (c + TB - 1) / TB;
    cnt[t] = c; coff[t] = c; woff[t] = nch;
    __syncthreads();
    #pragma unroll
    for (int s = 1; s < 256; s <<= 1) {
        int a = (t >= s) ? coff[t - s] : 0;
        int b = (t >= s) ? woff[t - s] : 0;
        __syncthreads();
        coff[t] += a; woff[t] += b;
        __syncthreads();
    }
    if (t < RN) {
        int off   = coff[t] - cnt[t];   // exclusive
        int wbase = woff[t] - nch;
        g_offset[t] = off;
        g_cursor[t] = 0;
        for (int ch = 0; ch < nch; ch++)
            g_work[wbase + ch] = make_int2(off + ch * TB, min(TB, c - ch * TB));
    }
    if (t == 255) g_nwork = woff[255];
}

__global__ void __launch_bounds__(HT) k_scatter(const int* __restrict__ triples) {
    __shared__ int h[4][RN];
    __shared__ int base[RN];
    __shared__ int lcur[RN];
    int t = threadIdx.x;
    for (int i = t; i < 4 * RN; i += HT) (&h[0][0])[i] = 0;
    __syncthreads();
    int i = blockIdx.x * HT + t;
    int r = triples[3 * i + 1];
    atomicAdd(&h[t & 3][r], 1);
    __syncthreads();
    for (int rr = t; rr < RN; rr += HT) {
        int cc = h[0][rr] + h[1][rr] + h[2][rr] + h[3][rr];
        base[rr] = cc ? atomicAdd(&g_cursor[rr], cc) : 0;
        lcur[rr] = 0;
    }
    __syncthreads();
    int p = base[r] + atomicAdd(&lcur[r], 1);
    g_sorted[g_offset[r] + p] = i;
}

// ---------------- main fused kernel ----------------

__device__ __forceinline__ void cp16(void* s, const void* g) {
    unsigned u = (unsigned)__cvta_generic_to_shared(s);
    asm volatile("cp.async.cg.shared.global [%0], [%1], 16;" :: "r"(u), "l"(g));
}

extern __shared__ float smem[];

__global__ void __launch_bounds__(NTH) k_main(
    const int* __restrict__ triples, const float* __restrict__ ent,
    const float* __restrict__ rel, const float* __restrict__ W,
    const float* __restrict__ cw, const float* __restrict__ cb,
    const float* __restrict__ fcw, const float* __restrict__ fcb,
    float* __restrict__ out)
{
    float* sX   = smem;                 // 48*132 (reused as C after GEMM)
    float* sW   = sX + ROWS * SXP;      // 2 x 16 x 128
    float* sFC  = sW + 4096;            // 6400
    float* sRel = sFC + 6400;           // 128
    float* sCw0 = sRel + DN;
    float* sCw1 = sCw0 + CN;
    float* sCw2 = sCw1 + CN;
    float* sCb  = sCw2 + CN;
    float* sRed = sCb + CN;             // 16
    int*   sEid = (int*)(sRed + 16);    // 48

    int bid = blockIdx.x;
    if (bid >= g_nwork) return;
    int tid = threadIdx.x;
    int2 wi = g_work[bid];
    int start = wi.x, cnt = wi.y;

    int r = triples[3 * g_sorted[start] + 1];
    const float* gw = W + (size_t)r * DN * DN;

    // group 0: rel row + W panel 0
    for (int i = tid; i < 32; i += NTH)
        cp16(sRel + i*4, rel + (size_t)r * DN + i*4);
    for (int i = tid; i < 512; i += NTH)
        cp16(sW + i*4, gw + i*4);
    asm volatile("cp.async.commit_group;");

    // group 1: fc_w (not needed until epilogue)
    for (int i = tid; i < 1600; i += NTH)
        cp16(sFC + i*4, fcw + i*4);
    asm volatile("cp.async.commit_group;");

    if (tid < CN) {
        sCw0[tid] = cw[tid*3 + 0];
        sCw1[tid] = cw[tid*3 + 1];
        sCw2[tid] = cw[tid*3 + 2];
        sCb[tid]  = cb[tid];
    }
    if (tid < ROWS) {
        int eid = 0;
        if (tid < 2*cnt) {
            int ti = g_sorted[start + (tid >> 1)];
            eid = triples[3*ti + ((tid & 1) ? 2 : 0)];
        }
        sEid[tid] = eid;
    }
    __syncthreads();

    // gather X rows (zero-pad unused rows)
    for (int e = tid; e < ROWS * 32; e += NTH) {
        int row = e >> 5, k4 = e & 31;
        float4 v = make_float4(0.f, 0.f, 0.f, 0.f);
        if (row < 2*cnt)
            v = *(const float4*)(ent + (size_t)sEid[row] * DN + k4*4);
        *(float4*)(sX + row * SXP + k4*4) = v;
    }

    int c = tid & 31, rg = tid >> 5;
    float4 acc[8];
    #pragma unroll
    for (int i = 0; i < 8; i++) acc[i] = make_float4(0.f, 0.f, 0.f, 0.f);

    const float* xbase = sX + rg * 8 * SXP;

    for (int p = 0; p < 8; p++) {
        if (p < 7) {
            const float* gp = gw + (p + 1) * 2048;
            float* sp = sW + ((p + 1) & 1) * 2048;
            for (int i = tid; i < 512; i += NTH)
                cp16(sp + i*4, gp + i*4);
            asm volatile("cp.async.commit_group;");
            if (p == 0)
                asm volatile("cp.async.wait_group 2;" ::: "memory");  // W0 done; FC+W1 in flight
            else
                asm volatile("cp.async.wait_group 1;" ::: "memory");  // W(p) done
        } else {
            asm volatile("cp.async.wait_group 0;" ::: "memory");
        }
        __syncthreads();
        const float* wp = sW + (p & 1) * 2048;
        const float* xp = xbase + p * 16;

        // 16 kk steps as 4 groups of 4; A loaded as float4 per row per group
        #pragma unroll
        for (int k4 = 0; k4 < 4; k4++) {
            float4 a[8];
            #pragma unroll
            for (int i = 0; i < 8; i++)
                a[i] = *(const float4*)(xp + i * SXP + k4 * 4);

            #pragma unroll
            for (int kk = 0; kk < 4; kk++) {
                float4 b = *(const float4*)(wp + (k4 * 4 + kk) * DN + c * 4);
                #pragma unroll
                for (int i = 0; i < 8; i++) {
                    float av = (kk == 0) ? a[i].x : (kk == 1) ? a[i].y
                              : (kk == 2) ? a[i].z : a[i].w;
                    acc[i].x = fmaf(av, b.x, acc[i].x);
                    acc[i].y = fmaf(av, b.y, acc[i].y);
                    acc[i].z = fmaf(av, b.z, acc[i].z);
                    acc[i].w = fmaf(av, b.w, acc[i].w);
                }
            }
        }
        __syncthreads();
    }

    // write C (projections) into sX region
    float* sC = sX;
    #pragma unroll
    for (int i = 0; i < 8; i++)
        *(float4*)(sC + (rg*8 + i) * SXP + c*4) = acc[i];
    __syncthreads();

    // epilogue: conv(3->50) + ReLU + FC dot, 4 triples per pass
    float fcb0 = fcb[0];
    int d = tid;
    float relv = (tid < DN) ? sRel[d] : 0.f;

    for (int u0 = 0; u0 < TB; u0 += 4) {
        float part0 = 0.f, part1 = 0.f, part2 = 0.f, part3 = 0.f;
        if (tid < DN) {
            float ph0 = sC[(2*u0 + 0)*SXP + d], pt0 = sC[(2*u0 + 1)*SXP + d];
            float ph1 = sC[(2*u0 + 2)*SXP + d], pt1 = sC[(2*u0 + 3)*SXP + d];
            float ph2 = sC[(2*u0 + 4)*SXP + d], pt2 = sC[(2*u0 + 5)*SXP + d];
            float ph3 = sC[(2*u0 + 6)*SXP + d], pt3 = sC[(2*u0 + 7)*SXP + d];
            #pragma unroll 10
            for (int cc = 0; cc < CN; cc++) {
                float w0 = sCw0[cc], w1 = sCw1[cc], w2 = sCw2[cc], bb = sCb[cc];
                float base = fmaf(w1, relv, bb);
                float fw = sFC[cc * DN + d];
                float s0 = fmaxf(fmaf(w0, ph0, fmaf(w2, pt0, base)), 0.f);
                float s1 = fmaxf(fmaf(w0, ph1, fmaf(w2, pt1, base)), 0.f);
                float s2 = fmaxf(fmaf(w0, ph2, fmaf(w2, pt2, base)), 0.f);
                float s3 = fmaxf(fmaf(w0, ph3, fmaf(w2, pt3, base)), 0.f);
                part0 = fmaf(s0, fw, part0);
                part1 = fmaf(s1, fw, part1);
                part2 = fmaf(s2, fw, part2);
                part3 = fmaf(s3, fw, part3);
            }
            #pragma unroll
            for (int o = 16; o; o >>= 1) {
                part0 += __shfl_xor_sync(0xffffffffu, part0, o);
                part1 += __shfl_xor_sync(0xffffffffu, part1, o);
                part2 += __shfl_xor_sync(0xffffffffu, part2, o);
                part3 += __shfl_xor_sync(0xffffffffu, part3, o);
            }
            if ((tid & 31) == 0) {
                int w = tid >> 5;
                sRed[w*4 + 0] = part0; sRed[w*4 + 1] = part1;
                sRed[w*4 + 2] = part2; sRed[w*4 + 3] = part3;
            }
        }
        __syncthreads();
        if (tid < 4) {
            int u = u0 + tid;
            if (u < cnt) {
                float v = sRed[tid] + sRed[4 + tid] + sRed[8 + tid] + sRed[12 + tid] + fcb0;
                out[g_sorted[start + u]] = v;
            }
        }
        __syncthreads();
    }
}

// ---------------- launch ----------------

extern "C" void kernel_launch(void* const* d_in, const int* in_sizes, int n_in,
                              void* d_out, int out_size)
{
    const int*   triples = (const int*)d_in[0];
    const float* ent     = (const float*)d_in[1];
    const float* rel     = (const float*)d_in[2];
    const float* W       = (const float*)d_in[3];
    const float* cw      = (const float*)d_in[4];
    const float* cb      = (const float*)d_in[5];
    const float* fcw     = (const float*)d_in[6];
    const float* fcb     = (const float*)d_in[7];
    float* out = (float*)d_out;

    size_t shbytes = (size_t)(ROWS*SXP + 4096 + 6400 + DN + 4*CN + 16) * 4 + ROWS * 4;
    cudaFuncSetAttribute(k_main, cudaFuncAttributeMaxDynamicSharedMemorySize, (int)(shbytes + 256));

    k_hist<<<HB, HT>>>(triples);
    k_scan<<<1, 256>>>();
    k_scatter<<<HB, HT>>>(triples);
    k_main<<<MAXWORK, NTH, shbytes>>>(triples, ent, rel, W, cw, cb, fcw, fcb, out);
}